// round 5
// baseline (speedup 1.0000x reference)
#include <cuda_runtime.h>
#include <cstdint>

#define S 2048
#define B 32
#define I 256
#define H 256
#define G4 1024
#define NCTA 128
#define NTHR2 256

// Static device scratch (no cudaMalloc allowed).
__device__ float g_Wp[I * G4];              // packed input weights  [k][colp]
__device__ float g_Up[H * G4];              // packed recurrent wts  [k][colp]
__device__ float g_bp[G4];                  // packed bias
__device__ float g_xg[(size_t)S * B * G4];  // input projections [t][cta][b][8]
__device__ float g_hbuf[2][B * H];          // ping-pong h  [parity][b][dim]
__device__ unsigned g_done[NCTA];           // per-CTA completed-step flags

// colp = cta*8 + g*2 + dd  -> gate g in {f,i,c,o}, hidden dim j = 2*cta + dd
__global__ void pack_kernel(
    const float* __restrict__ Wf, const float* __restrict__ Wi,
    const float* __restrict__ Wc, const float* __restrict__ Wo,
    const float* __restrict__ Uf, const float* __restrict__ Ui,
    const float* __restrict__ Uc, const float* __restrict__ Uo,
    const float* __restrict__ bf, const float* __restrict__ bi,
    const float* __restrict__ bc, const float* __restrict__ bo)
{
    int idx = blockIdx.x * blockDim.x + threadIdx.x;
    if (idx < I * G4) {
        int k    = idx >> 10;
        int colp = idx & 1023;
        int g    = (colp >> 1) & 3;
        int j    = ((colp >> 3) << 1) | (colp & 1);
        const float* W = (g == 0) ? Wf : (g == 1) ? Wi : (g == 2) ? Wc : Wo;
        const float* U = (g == 0) ? Uf : (g == 1) ? Ui : (g == 2) ? Uc : Uo;
        g_Wp[idx] = W[k * H + j];
        g_Up[idx] = U[k * H + j];
        if (k == 0) {
            const float* bv = (g == 0) ? bf : (g == 1) ? bi : (g == 2) ? bc : bo;
            g_bp[colp] = bv[j];
        }
    }
    if (idx < 2 * B * H) ((float*)g_hbuf)[idx] = 0.f;
    if (idx < NCTA) g_done[idx] = 0u;
}

// ---------------- Phase 1: xg = x @ Wp + bp, output [t][cta][b][8] ----------------
#define BM 64
#define BN 64
#define BK 16

__global__ __launch_bounds__(256) void gemm_xg_kernel(const float* __restrict__ x)
{
    __shared__ float As[BK][BM + 4];
    __shared__ float Bs[BK][BN];

    int tid = threadIdx.x;
    int r0 = blockIdx.y * BM;   // rows r = t*B + b
    int c0 = blockIdx.x * BN;
    int tr = tid >> 4, tc = tid & 15;

    int aRow = tid >> 2;
    int aK   = (tid & 3) << 2;
    int bK   = tid >> 4;
    int bC   = (tid & 15) << 2;

    int r  = r0 + aRow;
    int bb = r & 31;
    int tt = r >> 5;
    const float* aptr = x + ((size_t)bb * S + tt) * I + aK;

    float acc[4][4];
#pragma unroll
    for (int i2 = 0; i2 < 4; ++i2)
#pragma unroll
        for (int j2 = 0; j2 < 4; ++j2) acc[i2][j2] = 0.f;

    for (int k0 = 0; k0 < I; k0 += BK) {
        float4 av = *(const float4*)(aptr + k0);
        As[aK + 0][aRow] = av.x;
        As[aK + 1][aRow] = av.y;
        As[aK + 2][aRow] = av.z;
        As[aK + 3][aRow] = av.w;
        float4 bv = *(const float4*)(g_Wp + (size_t)(k0 + bK) * G4 + c0 + bC);
        *(float4*)&Bs[bK][bC] = bv;
        __syncthreads();
#pragma unroll
        for (int kk = 0; kk < BK; ++kk) {
            float4 a4 = *(const float4*)&As[kk][tr << 2];
            float4 b4 = *(const float4*)&Bs[kk][tc << 2];
            acc[0][0] = fmaf(a4.x, b4.x, acc[0][0]);
            acc[0][1] = fmaf(a4.x, b4.y, acc[0][1]);
            acc[0][2] = fmaf(a4.x, b4.z, acc[0][2]);
            acc[0][3] = fmaf(a4.x, b4.w, acc[0][3]);
            acc[1][0] = fmaf(a4.y, b4.x, acc[1][0]);
            acc[1][1] = fmaf(a4.y, b4.y, acc[1][1]);
            acc[1][2] = fmaf(a4.y, b4.z, acc[1][2]);
            acc[1][3] = fmaf(a4.y, b4.w, acc[1][3]);
            acc[2][0] = fmaf(a4.z, b4.x, acc[2][0]);
            acc[2][1] = fmaf(a4.z, b4.y, acc[2][1]);
            acc[2][2] = fmaf(a4.z, b4.z, acc[2][2]);
            acc[2][3] = fmaf(a4.z, b4.w, acc[2][3]);
            acc[3][0] = fmaf(a4.w, b4.x, acc[3][0]);
            acc[3][1] = fmaf(a4.w, b4.y, acc[3][1]);
            acc[3][2] = fmaf(a4.w, b4.z, acc[3][2]);
            acc[3][3] = fmaf(a4.w, b4.w, acc[3][3]);
        }
        __syncthreads();
    }

    int col  = c0 + (tc << 2);
    int ctab = col >> 3;
    int c7   = col & 7;           // 0 or 4 -> float4 stays inside 8-block
    float4 bias = *(const float4*)&g_bp[col];
#pragma unroll
    for (int i2 = 0; i2 < 4; ++i2) {
        int rr  = r0 + (tr << 2) + i2;
        int tt2 = rr >> 5;
        int bb2 = rr & 31;
        float4 o;
        o.x = acc[i2][0] + bias.x;
        o.y = acc[i2][1] + bias.y;
        o.z = acc[i2][2] + bias.z;
        o.w = acc[i2][3] + bias.w;
        *(float4*)(g_xg + (((size_t)tt2 * NCTA + ctab) * B + bb2) * 8 + c7) = o;
    }
}

// ---------------- Phase 2: persistent recurrence ----------------
__device__ __forceinline__ float sigmoidf_(float v) {
    return 1.f / (1.f + __expf(-v));
}

__global__ __launch_bounds__(NTHR2, 1) void lstm_kernel(float* __restrict__ out, int out_size)
{
    __shared__ float red[32][258];   // partials [ks][c*32+b], padded
    __shared__ float z_s[8][32];
    __shared__ float xs[8][33];      // staged xg [c][b]

    int cta  = blockIdx.x;
    int tid  = threadIdx.x;
    int ks   = tid & 31;     // k-pair slice (pair p = it*32 + ks)
    int bgrp = tid >> 5;     // batch quad: b = bgrp*4 + q

    // hoist U into registers (time-invariant): u2[it][c] = (U[c][2p], U[c][2p+1])
    unsigned long long u2[4][8];
#pragma unroll
    for (int it = 0; it < 4; ++it) {
        int p = it * 32 + ks;
        const float* lo = g_Up + (size_t)(2 * p) * G4 + cta * 8;
        const float* hi = lo + G4;
#pragma unroll
        for (int c = 0; c < 8; ++c) {
            unsigned l = __float_as_uint(lo[c]);
            unsigned h = __float_as_uint(hi[c]);
            u2[it][c] = ((unsigned long long)h << 32) | l;
        }
    }

    int dd = tid >> 5;       // gate threads (tid<64)
    int bb = tid & 31;
    int c2 = tid >> 5;       // stage-2 col (0..7)
    int b2 = tid & 31;       // stage-2 batch
    float cstate = 0.f;

    // prefetch xg for t=0
    float4 xv = make_float4(0.f, 0.f, 0.f, 0.f);
    int pb = tid >> 1, phalf = tid & 1;
    if (tid < 64)
        xv = __ldg((const float4*)(g_xg + (((size_t)0 * NCTA + cta) * B + pb) * 8 + phalf * 4));

    volatile unsigned* gd = g_done;
    __syncthreads();

    for (int t = 0; t < S; ++t) {
        // park this step's xg; prefetch next step's
        if (tid < 64) {
            xs[phalf * 4 + 0][pb] = xv.x;
            xs[phalf * 4 + 1][pb] = xv.y;
            xs[phalf * 4 + 2][pb] = xv.z;
            xs[phalf * 4 + 3][pb] = xv.w;
            if (t + 1 < S)
                xv = __ldg((const float4*)(g_xg + (((size_t)(t + 1) * NCTA + cta) * B + pb) * 8 + phalf * 4));
        }
        // wait for all producers to have finished step t-1
        if (t > 0 && tid < NCTA) {
            while (gd[tid] < (unsigned)t) {}
        }
        __syncthreads();

        // load h_{t-1} pairs: [b][dim] layout, contiguous in dim -> coalesced LDG.64
        const unsigned long long* hsrc =
            (const unsigned long long*)g_hbuf[(t + 1) & 1];
        unsigned long long h2[4][4];
#pragma unroll
        for (int it = 0; it < 4; ++it)
#pragma unroll
            for (int q = 0; q < 4; ++q)
                h2[it][q] = __ldcg(hsrc + (size_t)(bgrp * 4 + q) * 128 + it * 32 + ks);

        unsigned long long acc[8][4];
#pragma unroll
        for (int c = 0; c < 8; ++c)
#pragma unroll
            for (int q = 0; q < 4; ++q) acc[c][q] = 0ull;

#pragma unroll
        for (int it = 0; it < 4; ++it)
#pragma unroll
            for (int c = 0; c < 8; ++c) {
                unsigned long long u = u2[it][c];
#pragma unroll
                for (int q = 0; q < 4; ++q)
                    asm("fma.rn.f32x2 %0, %1, %2, %0;"
                        : "+l"(acc[c][q]) : "l"(u), "l"(h2[it][q]));
            }

        // horizontal add of pair lanes, store partials (STS.64 over q-pairs)
#pragma unroll
        for (int c = 0; c < 8; ++c) {
            float s[4];
#pragma unroll
            for (int q = 0; q < 4; ++q) {
                unsigned long long v = acc[c][q];
                s[q] = __uint_as_float((unsigned)v) + __uint_as_float((unsigned)(v >> 32));
            }
            *(float2*)&red[ks][c * 32 + bgrp * 4 + 0] = make_float2(s[0], s[1]);
            *(float2*)&red[ks][c * 32 + bgrp * 4 + 2] = make_float2(s[2], s[3]);
        }
        __syncthreads();

        // stage-2 reduce over 32 k-slices: thread -> (c2, b2)
        {
            float p0 = 0.f, p1 = 0.f, p2 = 0.f, p3 = 0.f;
#pragma unroll
            for (int q = 0; q < 32; q += 4) {
                p0 += red[q + 0][c2 * 32 + b2];
                p1 += red[q + 1][c2 * 32 + b2];
                p2 += red[q + 2][c2 * 32 + b2];
                p3 += red[q + 3][c2 * 32 + b2];
            }
            z_s[c2][b2] = (p0 + p1) + (p2 + p3) + xs[c2][b2];
        }
        __syncthreads();

        float hh = 0.f;
        if (tid < 64) {
            float zf = z_s[0 + dd][bb];
            float zi = z_s[2 + dd][bb];
            float zc = z_s[4 + dd][bb];
            float zo = z_s[6 + dd][bb];
            float f  = sigmoidf_(zf);
            float ii = sigmoidf_(zi);
            float gg = tanhf(zc);
            float oo = sigmoidf_(zo);
            cstate = fmaf(f, cstate, ii * gg);
            hh = oo * tanhf(cstate);
            g_hbuf[t & 1][bb * H + cta * 2 + dd] = hh;   // [b][dim]
        }
        __syncthreads();

        // release this step, then do off-critical-path output stores
        if (tid == 0) {
            __threadfence();
            *(volatile unsigned*)&g_done[cta] = (unsigned)(t + 1);
        }
        if (tid < 64) {
            int dim = cta * 2 + dd;
            out[(size_t)bb * (S * H) + (size_t)t * H + dim] = hh;
            if (t == S - 1) {
                size_t base = (size_t)B * S * H;
                if ((size_t)out_size >= base + 2 * (size_t)B * H) {
                    out[base + (size_t)bb * H + dim] = hh;
                    out[base + (size_t)B * H + (size_t)bb * H + dim] = cstate;
                }
            }
        }
    }
}

extern "C" void kernel_launch(void* const* d_in, const int* in_sizes, int n_in,
                              void* d_out, int out_size) {
    (void)in_sizes; (void)n_in;
    const float* x  = (const float*)d_in[0];
    const float* Wf = (const float*)d_in[1];
    const float* Uf = (const float*)d_in[2];
    const float* bf = (const float*)d_in[3];
    const float* Wi = (const float*)d_in[4];
    const float* Ui = (const float*)d_in[5];
    const float* bi = (const float*)d_in[6];
    const float* Wo = (const float*)d_in[7];
    const float* Uo = (const float*)d_in[8];
    const float* bo = (const float*)d_in[9];
    const float* Wc = (const float*)d_in[10];
    const float* Uc = (const float*)d_in[11];
    const float* bc = (const float*)d_in[12];

    pack_kernel<<<1024, 256>>>(Wf, Wi, Wc, Wo, Uf, Ui, Uc, Uo, bf, bi, bc, bo);
    gemm_xg_kernel<<<dim3(G4 / BN, (S * B) / BM), 256>>>(x);
    lstm_kernel<<<NCTA, NTHR2>>>((float*)d_out, out_size);
}

// round 7
// speedup vs baseline: 2.5669x; 2.5669x over previous
#include <cuda_runtime.h>
#include <cstdint>

#define S 2048
#define B 32
#define I 256
#define H 256
#define G4 1024
#define NCTA 128
#define NTHR2 512

// Static device scratch (no cudaMalloc allowed).
__device__ float g_Wp[I * G4];              // packed input weights  [k][colp]
__device__ float g_Up[H * G4];              // packed recurrent wts  [k][colp]
__device__ float g_bp[G4];                  // packed bias
__device__ float g_xg[(size_t)S * B * G4];  // input projections [t][cta][b][8]
__device__ float g_hbuf[2][B * H];          // ping-pong h  [parity][b][dim]
__device__ unsigned g_ctr[S];               // per-step arrival counters

// colp = cta*8 + g*2 + dd  -> gate g in {f,i,c,o}, hidden dim j = 2*cta + dd
__global__ void pack_kernel(
    const float* __restrict__ Wf, const float* __restrict__ Wi,
    const float* __restrict__ Wc, const float* __restrict__ Wo,
    const float* __restrict__ Uf, const float* __restrict__ Ui,
    const float* __restrict__ Uc, const float* __restrict__ Uo,
    const float* __restrict__ bf, const float* __restrict__ bi,
    const float* __restrict__ bc, const float* __restrict__ bo)
{
    int idx = blockIdx.x * blockDim.x + threadIdx.x;
    if (idx < I * G4) {
        int k    = idx >> 10;
        int colp = idx & 1023;
        int g    = (colp >> 1) & 3;
        int j    = ((colp >> 3) << 1) | (colp & 1);
        const float* W = (g == 0) ? Wf : (g == 1) ? Wi : (g == 2) ? Wc : Wo;
        const float* U = (g == 0) ? Uf : (g == 1) ? Ui : (g == 2) ? Uc : Uo;
        g_Wp[idx] = W[k * H + j];
        g_Up[idx] = U[k * H + j];
        if (k == 0) {
            const float* bv = (g == 0) ? bf : (g == 1) ? bi : (g == 2) ? bc : bo;
            g_bp[colp] = bv[j];
        }
    }
    if (idx < 2 * B * H) ((float*)g_hbuf)[idx] = 0.f;
    if (idx < S) g_ctr[idx] = 0u;
}

// ---------------- Phase 1: xg = x @ Wp + bp, output [t][cta][b][8] ----------------
#define BM 64
#define BN 64
#define BK 16

__global__ __launch_bounds__(256) void gemm_xg_kernel(const float* __restrict__ x)
{
    __shared__ float As[BK][BM + 4];
    __shared__ float Bs[BK][BN];

    int tid = threadIdx.x;
    int r0 = blockIdx.y * BM;   // rows r = t*B + b
    int c0 = blockIdx.x * BN;
    int tr = tid >> 4, tc = tid & 15;

    int aRow = tid >> 2;
    int aK   = (tid & 3) << 2;
    int bK   = tid >> 4;
    int bC   = (tid & 15) << 2;

    int r  = r0 + aRow;
    int bb = r & 31;
    int tt = r >> 5;
    const float* aptr = x + ((size_t)bb * S + tt) * I + aK;

    float acc[4][4];
#pragma unroll
    for (int i2 = 0; i2 < 4; ++i2)
#pragma unroll
        for (int j2 = 0; j2 < 4; ++j2) acc[i2][j2] = 0.f;

    for (int k0 = 0; k0 < I; k0 += BK) {
        float4 av = *(const float4*)(aptr + k0);
        As[aK + 0][aRow] = av.x;
        As[aK + 1][aRow] = av.y;
        As[aK + 2][aRow] = av.z;
        As[aK + 3][aRow] = av.w;
        float4 bv = *(const float4*)(g_Wp + (size_t)(k0 + bK) * G4 + c0 + bC);
        *(float4*)&Bs[bK][bC] = bv;
        __syncthreads();
#pragma unroll
        for (int kk = 0; kk < BK; ++kk) {
            float4 a4 = *(const float4*)&As[kk][tr << 2];
            float4 b4 = *(const float4*)&Bs[kk][tc << 2];
            acc[0][0] = fmaf(a4.x, b4.x, acc[0][0]);
            acc[0][1] = fmaf(a4.x, b4.y, acc[0][1]);
            acc[0][2] = fmaf(a4.x, b4.z, acc[0][2]);
            acc[0][3] = fmaf(a4.x, b4.w, acc[0][3]);
            acc[1][0] = fmaf(a4.y, b4.x, acc[1][0]);
            acc[1][1] = fmaf(a4.y, b4.y, acc[1][1]);
            acc[1][2] = fmaf(a4.y, b4.z, acc[1][2]);
            acc[1][3] = fmaf(a4.y, b4.w, acc[1][3]);
            acc[2][0] = fmaf(a4.z, b4.x, acc[2][0]);
            acc[2][1] = fmaf(a4.z, b4.y, acc[2][1]);
            acc[2][2] = fmaf(a4.z, b4.z, acc[2][2]);
            acc[2][3] = fmaf(a4.z, b4.w, acc[2][3]);
            acc[3][0] = fmaf(a4.w, b4.x, acc[3][0]);
            acc[3][1] = fmaf(a4.w, b4.y, acc[3][1]);
            acc[3][2] = fmaf(a4.w, b4.z, acc[3][2]);
            acc[3][3] = fmaf(a4.w, b4.w, acc[3][3]);
        }
        __syncthreads();
    }

    int col  = c0 + (tc << 2);
    int ctab = col >> 3;
    int c7   = col & 7;           // 0 or 4 -> float4 stays inside 8-block
    float4 bias = *(const float4*)&g_bp[col];
#pragma unroll
    for (int i2 = 0; i2 < 4; ++i2) {
        int rr  = r0 + (tr << 2) + i2;
        int tt2 = rr >> 5;
        int bb2 = rr & 31;
        float4 o;
        o.x = acc[i2][0] + bias.x;
        o.y = acc[i2][1] + bias.y;
        o.z = acc[i2][2] + bias.z;
        o.w = acc[i2][3] + bias.w;
        *(float4*)(g_xg + (((size_t)tt2 * NCTA + ctab) * B + bb2) * 8 + c7) = o;
    }
}

// ---------------- Phase 2: persistent recurrence ----------------
__device__ __forceinline__ float sigmoidf_(float v) {
    return 1.f / (1.f + __expf(-v));
}

__global__ __launch_bounds__(NTHR2, 1) void lstm_kernel(float* __restrict__ out, int out_size)
{
    __shared__ float red[32][257];   // partials [ks][c*32+b], stride 257 -> conflict-free
    __shared__ float z_s[8][32];
    __shared__ float xs[8][33];      // staged xg [c][b]

    int cta  = blockIdx.x;
    int tid  = threadIdx.x;
    int ks   = tid & 31;          // k-quad slice: quad qd = it*32 + ks, it in {0,1}
    int cgrp = (tid >> 5) & 1;    // col half: cols cgrp*4 .. +3
    int bgrp = tid >> 6;          // batch quad: b = bgrp*4 + q

    // hoist U into registers (time-invariant):
    // u2[it][ph][cc] = (U[4qd+2ph][col], U[4qd+2ph+1][col]) packed as f32x2
    unsigned long long u2[2][2][4];
#pragma unroll
    for (int it = 0; it < 2; ++it)
#pragma unroll
        for (int ph = 0; ph < 2; ++ph)
#pragma unroll
            for (int cc = 0; cc < 4; ++cc) {
                int col = cta * 8 + cgrp * 4 + cc;
                int k0  = (it * 32 + ks) * 4 + ph * 2;
                unsigned lo = __float_as_uint(g_Up[(size_t)k0 * G4 + col]);
                unsigned hi = __float_as_uint(g_Up[(size_t)(k0 + 1) * G4 + col]);
                u2[it][ph][cc] = ((unsigned long long)hi << 32) | lo;
            }

    int dd = tid >> 5;            // gate threads (tid<64): dd 0..1
    int bb = tid & 31;
    float cstate = 0.f;

    // prefetch xg for t=0 (tid<64)
    float4 xv = make_float4(0.f, 0.f, 0.f, 0.f);
    int pb = tid >> 1, phalf = tid & 1;
    if (tid < 64)
        xv = __ldg((const float4*)(g_xg + (((size_t)0 * NCTA + cta) * B + pb) * 8 + phalf * 4));

    __syncthreads();

    for (int t = 0; t < S; ++t) {
        // park this step's xg; prefetch next step's
        if (tid < 64) {
            xs[phalf * 4 + 0][pb] = xv.x;
            xs[phalf * 4 + 1][pb] = xv.y;
            xs[phalf * 4 + 2][pb] = xv.z;
            xs[phalf * 4 + 3][pb] = xv.w;
            if (t + 1 < S)
                xv = __ldg((const float4*)(g_xg + (((size_t)(t + 1) * NCTA + cta) * B + pb) * 8 + phalf * 4));
        }
        // wait for all producers to have finished step t-1 (single-thread poll)
        if (t > 0 && tid == 0) {
            volatile unsigned* p = &g_ctr[t - 1];
            while (*p < NCTA) {}
            __threadfence();   // acquire
        }
        __syncthreads();

        // load h_{t-1}: [b][dim] layout -> coalesced 16B quad loads (L2, bypass L1)
        const ulonglong2* hsrc = (const ulonglong2*)g_hbuf[(t + 1) & 1];
        ulonglong2 h2[2][4];
#pragma unroll
        for (int it = 0; it < 2; ++it)
#pragma unroll
            for (int q = 0; q < 4; ++q)
                h2[it][q] = __ldcg(hsrc + (size_t)(bgrp * 4 + q) * 64 + it * 32 + ks);

        unsigned long long acc[4][4];
#pragma unroll
        for (int cc = 0; cc < 4; ++cc)
#pragma unroll
            for (int q = 0; q < 4; ++q) acc[cc][q] = 0ull;

#pragma unroll
        for (int it = 0; it < 2; ++it)
#pragma unroll
            for (int q = 0; q < 4; ++q) {
                unsigned long long hx = h2[it][q].x;
                unsigned long long hy = h2[it][q].y;
#pragma unroll
                for (int cc = 0; cc < 4; ++cc) {
                    asm("fma.rn.f32x2 %0, %1, %2, %0;"
                        : "+l"(acc[cc][q]) : "l"(u2[it][0][cc]), "l"(hx));
                    asm("fma.rn.f32x2 %0, %1, %2, %0;"
                        : "+l"(acc[cc][q]) : "l"(u2[it][1][cc]), "l"(hy));
                }
            }

        // horizontal add of pair lanes, store partials (conflict-free: stride 257)
#pragma unroll
        for (int cc = 0; cc < 4; ++cc)
#pragma unroll
            for (int q = 0; q < 4; ++q) {
                unsigned long long v = acc[cc][q];
                float s = __uint_as_float((unsigned)v) + __uint_as_float((unsigned)(v >> 32));
                red[ks][(cgrp * 4 + cc) * 32 + bgrp * 4 + q] = s;
            }
        __syncthreads();

        // stage-2 reduce over 32 k-slices: thread tid<256 -> (c2, b2), col index = tid
        if (tid < 256) {
            float p0 = 0.f, p1 = 0.f, p2 = 0.f, p3 = 0.f;
#pragma unroll
            for (int q = 0; q < 32; q += 4) {
                p0 += red[q + 0][tid];
                p1 += red[q + 1][tid];
                p2 += red[q + 2][tid];
                p3 += red[q + 3][tid];
            }
            z_s[tid >> 5][tid & 31] = (p0 + p1) + (p2 + p3) + xs[tid >> 5][tid & 31];
        }
        __syncthreads();

        float hh = 0.f;
        if (tid < 64) {
            float zf = z_s[0 + dd][bb];
            float zi = z_s[2 + dd][bb];
            float zc = z_s[4 + dd][bb];
            float zo = z_s[6 + dd][bb];
            float f  = sigmoidf_(zf);
            float ii = sigmoidf_(zi);
            float gg = tanhf(zc);
            float oo = sigmoidf_(zo);
            cstate = fmaf(f, cstate, ii * gg);
            hh = oo * tanhf(cstate);
            g_hbuf[t & 1][bb * H + cta * 2 + dd] = hh;   // [b][dim]
        }
        __syncthreads();

        // release this step, then off-critical-path output stores
        if (tid == 0) {
            __threadfence();
            atomicAdd(&g_ctr[t], 1u);
        }
        if (tid < 64) {
            int dim = cta * 2 + dd;
            out[(size_t)bb * (S * H) + (size_t)t * H + dim] = hh;
            if (t == S - 1) {
                size_t base = (size_t)B * S * H;
                if ((size_t)out_size >= base + 2 * (size_t)B * H) {
                    out[base + (size_t)bb * H + dim] = hh;
                    out[base + (size_t)B * H + (size_t)bb * H + dim] = cstate;
                }
            }
        }
    }
}

extern "C" void kernel_launch(void* const* d_in, const int* in_sizes, int n_in,
                              void* d_out, int out_size) {
    (void)in_sizes; (void)n_in;
    const float* x  = (const float*)d_in[0];
    const float* Wf = (const float*)d_in[1];
    const float* Uf = (const float*)d_in[2];
    const float* bf = (const float*)d_in[3];
    const float* Wi = (const float*)d_in[4];
    const float* Ui = (const float*)d_in[5];
    const float* bi = (const float*)d_in[6];
    const float* Wo = (const float*)d_in[7];
    const float* Uo = (const float*)d_in[8];
    const float* bo = (const float*)d_in[9];
    const float* Wc = (const float*)d_in[10];
    const float* Uc = (const float*)d_in[11];
    const float* bc = (const float*)d_in[12];

    pack_kernel<<<1024, 256>>>(Wf, Wi, Wc, Wo, Uf, Ui, Uc, Uo, bf, bi, bc, bo);
    gemm_xg_kernel<<<dim3(G4 / BN, (S * B) / BM), 256>>>(x);
    lstm_kernel<<<NCTA, NTHR2>>>((float*)d_out, out_size);
}

// round 8
// speedup vs baseline: 2.6041x; 1.0145x over previous
#include <cuda_runtime.h>
#include <cstdint>

#define S 2048
#define B 32
#define I 256
#define H 256
#define G4 1024
#define NCTA 128
#define NTHR2 512
#define GB 8      // batch groups
#define GD 16     // CTAs per group

// Static device scratch (no cudaMalloc allowed).
__device__ float g_Wp[I * G4];                 // packed input weights  [k][colp]
__device__ float g_Up[H * G4];                 // packed recurrent wts  [k][colp]
__device__ float g_bp[G4];                     // packed bias
__device__ float g_xg[(size_t)S * B * G4];     // input projections [t][cta][bq][64]
__device__ float g_hseq[(size_t)(S + 1) * B * H];  // h history [t][b][dim]; slot 0 = zeros
__device__ unsigned g_ctr[GB * S];             // per-(group,step) arrival counters

// colp mapping: gate = colp&3 (0=f,1=i,2=c,3=o), jl = (colp>>2)&15, l = colp>>6
// hidden dim j = l*16 + jl. CTA (g,l) owns batches 4g..4g+3 and cols l*64..l*64+63.
__global__ void pack_kernel(
    const float* __restrict__ Wf, const float* __restrict__ Wi,
    const float* __restrict__ Wc, const float* __restrict__ Wo,
    const float* __restrict__ Uf, const float* __restrict__ Ui,
    const float* __restrict__ Uc, const float* __restrict__ Uo,
    const float* __restrict__ bf, const float* __restrict__ bi,
    const float* __restrict__ bc, const float* __restrict__ bo)
{
    int idx = blockIdx.x * blockDim.x + threadIdx.x;
    if (idx < I * G4) {
        int k    = idx >> 10;
        int colp = idx & 1023;
        int g    = colp & 3;
        int jl   = (colp >> 2) & 15;
        int l    = colp >> 6;
        int j    = l * 16 + jl;
        const float* W = (g == 0) ? Wf : (g == 1) ? Wi : (g == 2) ? Wc : Wo;
        const float* U = (g == 0) ? Uf : (g == 1) ? Ui : (g == 2) ? Uc : Uo;
        g_Wp[idx] = W[k * H + j];
        g_Up[idx] = U[k * H + j];
        if (k == 0) {
            const float* bv = (g == 0) ? bf : (g == 1) ? bi : (g == 2) ? bc : bo;
            g_bp[colp] = bv[j];
        }
    }
    if (idx < B * H) g_hseq[idx] = 0.f;     // slot 0 (h_{-1} = 0)
    if (idx < GB * S) g_ctr[idx] = 0u;
}

// ---------------- Phase 1: xg = x @ Wp + bp, output [t][cta][bq][64] ----------------
#define BM 64
#define BN 64
#define BK 16

__global__ __launch_bounds__(256) void gemm_xg_kernel(const float* __restrict__ x)
{
    __shared__ float As[BK][BM + 4];
    __shared__ float Bs[BK][BN];

    int tid = threadIdx.x;
    int r0 = blockIdx.y * BM;   // rows r = t*B + b
    int c0 = blockIdx.x * BN;
    int tr = tid >> 4, tc = tid & 15;

    int aRow = tid >> 2;
    int aK   = (tid & 3) << 2;
    int bK   = tid >> 4;
    int bC   = (tid & 15) << 2;

    int r  = r0 + aRow;
    int bb = r & 31;
    int tt = r >> 5;
    const float* aptr = x + ((size_t)bb * S + tt) * I + aK;

    float acc[4][4];
#pragma unroll
    for (int i2 = 0; i2 < 4; ++i2)
#pragma unroll
        for (int j2 = 0; j2 < 4; ++j2) acc[i2][j2] = 0.f;

    for (int k0 = 0; k0 < I; k0 += BK) {
        float4 av = *(const float4*)(aptr + k0);
        As[aK + 0][aRow] = av.x;
        As[aK + 1][aRow] = av.y;
        As[aK + 2][aRow] = av.z;
        As[aK + 3][aRow] = av.w;
        float4 bv = *(const float4*)(g_Wp + (size_t)(k0 + bK) * G4 + c0 + bC);
        *(float4*)&Bs[bK][bC] = bv;
        __syncthreads();
#pragma unroll
        for (int kk = 0; kk < BK; ++kk) {
            float4 a4 = *(const float4*)&As[kk][tr << 2];
            float4 b4 = *(const float4*)&Bs[kk][tc << 2];
            acc[0][0] = fmaf(a4.x, b4.x, acc[0][0]);
            acc[0][1] = fmaf(a4.x, b4.y, acc[0][1]);
            acc[0][2] = fmaf(a4.x, b4.z, acc[0][2]);
            acc[0][3] = fmaf(a4.x, b4.w, acc[0][3]);
            acc[1][0] = fmaf(a4.y, b4.x, acc[1][0]);
            acc[1][1] = fmaf(a4.y, b4.y, acc[1][1]);
            acc[1][2] = fmaf(a4.y, b4.z, acc[1][2]);
            acc[1][3] = fmaf(a4.y, b4.w, acc[1][3]);
            acc[2][0] = fmaf(a4.z, b4.x, acc[2][0]);
            acc[2][1] = fmaf(a4.z, b4.y, acc[2][1]);
            acc[2][2] = fmaf(a4.z, b4.z, acc[2][2]);
            acc[2][3] = fmaf(a4.z, b4.w, acc[2][3]);
            acc[3][0] = fmaf(a4.w, b4.x, acc[3][0]);
            acc[3][1] = fmaf(a4.w, b4.y, acc[3][1]);
            acc[3][2] = fmaf(a4.w, b4.z, acc[3][2]);
            acc[3][3] = fmaf(a4.w, b4.w, acc[3][3]);
        }
        __syncthreads();
    }

    int col = c0 + (tc << 2);         // global packed col, 4-aligned
    int l   = col >> 6;
    int c63 = col & 63;               // stays within 64-block for the float4
    float4 bias = *(const float4*)&g_bp[col];
#pragma unroll
    for (int i2 = 0; i2 < 4; ++i2) {
        int rr  = r0 + (tr << 2) + i2;
        int tt2 = rr >> 5;
        int bb2 = rr & 31;
        int grp = bb2 >> 2;
        int bq  = bb2 & 3;
        float4 o;
        o.x = acc[i2][0] + bias.x;
        o.y = acc[i2][1] + bias.y;
        o.z = acc[i2][2] + bias.z;
        o.w = acc[i2][3] + bias.w;
        *(float4*)(g_xg + (((size_t)tt2 * NCTA + grp * GD + l) * 4 + bq) * 64 + c63) = o;
    }
}

// ---------------- Phase 2: persistent recurrence ----------------
__device__ __forceinline__ float sig_(float v) {
    return __fdividef(1.f, 1.f + __expf(-v));
}
__device__ __forceinline__ float tanh_(float v) {
    return 1.f - __fdividef(2.f, 1.f + __expf(2.f * v));
}

__global__ __launch_bounds__(NTHR2, 1) void lstm_kernel(float* __restrict__ out, int out_size)
{
    __shared__ float xs[64][4];       // staged xg [col64][bq]
    __shared__ float z_s[16][4][4];   // [dimw][gate][bq]

    int cta  = blockIdx.x;
    int g    = cta >> 4;              // batch group
    int l    = cta & 15;              // dim slice
    int tid  = threadIdx.x;
    int lane = tid & 31;
    int w    = tid >> 5;              // warp -> local dim w, gates cols w*4..w*4+3

    // hoist U into registers (time-invariant):
    // u2[iq][pp][cc] = (U[k][col], U[k+1][col]), k = (iq*32+lane)*4 + pp*2,
    // col = l*64 + w*4 + cc
    unsigned long long u2[2][2][4];
#pragma unroll
    for (int iq = 0; iq < 2; ++iq)
#pragma unroll
        for (int pp = 0; pp < 2; ++pp)
#pragma unroll
            for (int cc = 0; cc < 4; ++cc) {
                int col = l * 64 + w * 4 + cc;
                int k   = (iq * 32 + lane) * 4 + pp * 2;
                unsigned lo = __float_as_uint(g_Up[(size_t)k * G4 + col]);
                unsigned hi = __float_as_uint(g_Up[(size_t)(k + 1) * G4 + col]);
                u2[iq][pp][cc] = ((unsigned long long)hi << 32) | lo;
            }

    // gate threads (tid<64): dimw = tid>>2, bq = tid&3
    int dimw = tid >> 2;
    int bq_g = tid & 3;
    float cstate = 0.f;

    // xg prefetch threads (tid<64): bq = tid>>4, col offset = (tid&15)*4
    int pbq = tid >> 4;
    int pc  = (tid & 15) * 4;
    float4 xv = make_float4(0.f, 0.f, 0.f, 0.f);
    if (tid < 64)
        xv = __ldg((const float4*)(g_xg + (((size_t)0 * NCTA + cta) * 4 + pbq) * 64 + pc));

    volatile unsigned* vctr = g_ctr;
    __syncthreads();

    for (int t = 0; t < S; ++t) {
        // park this step's xg; prefetch next step's
        if (tid < 64) {
            xs[pc + 0][pbq] = xv.x;
            xs[pc + 1][pbq] = xv.y;
            xs[pc + 2][pbq] = xv.z;
            xs[pc + 3][pbq] = xv.w;
            if (t + 1 < S)
                xv = __ldg((const float4*)(g_xg + (((size_t)(t + 1) * NCTA + cta) * 4 + pbq) * 64 + pc));
        }
        // wait for our group's 16 producers to finish step t-1
        if (t > 0 && tid == 0) {
            volatile unsigned* p = &vctr[g * S + (t - 1)];
            while (*p < GD) {}
            __threadfence();   // acquire; emits CCTL.IVALL -> L1 safe for h loads
        }
        __syncthreads();

        // load h_{t-1} slice (4 batches x 256 dims); same 4KB across all 16 warps -> L1 hits
        const float* hs = g_hseq + (size_t)t * (B * H) + (size_t)(g * 4) * H;
        float4 hq[2][4];
#pragma unroll
        for (int iq = 0; iq < 2; ++iq)
#pragma unroll
            for (int bq = 0; bq < 4; ++bq)
                hq[iq][bq] = *(const float4*)(hs + bq * H + (iq * 32 + lane) * 4);

        unsigned long long acc[4][4];   // [cc][bq]
#pragma unroll
        for (int cc = 0; cc < 4; ++cc)
#pragma unroll
            for (int bq = 0; bq < 4; ++bq) acc[cc][bq] = 0ull;

#pragma unroll
        for (int iq = 0; iq < 2; ++iq)
#pragma unroll
            for (int bq = 0; bq < 4; ++bq) {
                unsigned long long hx =
                    ((unsigned long long)__float_as_uint(hq[iq][bq].y) << 32) | __float_as_uint(hq[iq][bq].x);
                unsigned long long hy =
                    ((unsigned long long)__float_as_uint(hq[iq][bq].w) << 32) | __float_as_uint(hq[iq][bq].z);
#pragma unroll
                for (int cc = 0; cc < 4; ++cc) {
                    asm("fma.rn.f32x2 %0, %1, %2, %0;"
                        : "+l"(acc[cc][bq]) : "l"(u2[iq][0][cc]), "l"(hx));
                    asm("fma.rn.f32x2 %0, %1, %2, %0;"
                        : "+l"(acc[cc][bq]) : "l"(u2[iq][1][cc]), "l"(hy));
                }
            }

        // horizontal pair add -> v[m], m = cc*4+bq
        float v[16];
#pragma unroll
        for (int cc = 0; cc < 4; ++cc)
#pragma unroll
            for (int bq = 0; bq < 4; ++bq) {
                unsigned long long a = acc[cc][bq];
                v[cc * 4 + bq] =
                    __uint_as_float((unsigned)a) + __uint_as_float((unsigned)(a >> 32));
            }

        // warp butterfly reduction over 32 lanes (k-slices), 16 outputs
        {
            bool h4 = (lane & 16) != 0;
#pragma unroll
            for (int m = 0; m < 8; ++m) {
                float send = h4 ? v[m] : v[m + 8];
                float recv = __shfl_xor_sync(0xffffffffu, send, 16);
                v[m] = (h4 ? v[m + 8] : v[m]) + recv;
            }
            bool h3 = (lane & 8) != 0;
#pragma unroll
            for (int m = 0; m < 4; ++m) {
                float send = h3 ? v[m] : v[m + 4];
                float recv = __shfl_xor_sync(0xffffffffu, send, 8);
                v[m] = (h3 ? v[m + 4] : v[m]) + recv;
            }
            bool h2b = (lane & 4) != 0;
#pragma unroll
            for (int m = 0; m < 2; ++m) {
                float send = h2b ? v[m] : v[m + 2];
                float recv = __shfl_xor_sync(0xffffffffu, send, 4);
                v[m] = (h2b ? v[m + 2] : v[m]) + recv;
            }
            bool h1 = (lane & 2) != 0;
            {
                float send = h1 ? v[0] : v[1];
                float recv = __shfl_xor_sync(0xffffffffu, send, 2);
                v[0] = (h1 ? v[1] : v[0]) + recv;
            }
            v[0] += __shfl_xor_sync(0xffffffffu, v[0], 1);
        }
        // lane's final output index
        if ((lane & 1) == 0) {
            int m = ((lane >> 4) & 1) * 8 + ((lane >> 3) & 1) * 4 +
                    ((lane >> 2) & 1) * 2 + ((lane >> 1) & 1);
            z_s[w][m >> 2][m & 3] = v[0];
        }
        __syncthreads();

        float hh = 0.f;
        if (tid < 64) {
            float zf = z_s[dimw][0][bq_g] + xs[dimw * 4 + 0][bq_g];
            float zi = z_s[dimw][1][bq_g] + xs[dimw * 4 + 1][bq_g];
            float zc = z_s[dimw][2][bq_g] + xs[dimw * 4 + 2][bq_g];
            float zo = z_s[dimw][3][bq_g] + xs[dimw * 4 + 3][bq_g];
            float f  = sig_(zf);
            float ii = sig_(zi);
            float gg = tanh_(zc);
            float oo = sig_(zo);
            cstate = fmaf(f, cstate, ii * gg);
            hh = oo * tanh_(cstate);
            // write h_t into history slot t+1
            g_hseq[(size_t)(t + 1) * (B * H) + (size_t)(g * 4 + bq_g) * H + l * 16 + dimw] = hh;
        }
        __syncthreads();

        // release this step for our group, then off-critical-path output stores
        if (tid == 0) {
            __threadfence();
            atomicAdd(&g_ctr[g * S + t], 1u);
        }
        if (tid < 64) {
            int b   = g * 4 + bq_g;
            int dim = l * 16 + dimw;
            out[(size_t)b * (S * H) + (size_t)t * H + dim] = hh;
            if (t == S - 1) {
                size_t base = (size_t)B * S * H;
                if ((size_t)out_size >= base + 2 * (size_t)B * H) {
                    out[base + (size_t)b * H + dim] = hh;
                    out[base + (size_t)B * H + (size_t)b * H + dim] = cstate;
                }
            }
        }
    }
}

extern "C" void kernel_launch(void* const* d_in, const int* in_sizes, int n_in,
                              void* d_out, int out_size) {
    (void)in_sizes; (void)n_in;
    const float* x  = (const float*)d_in[0];
    const float* Wf = (const float*)d_in[1];
    const float* Uf = (const float*)d_in[2];
    const float* bf = (const float*)d_in[3];
    const float* Wi = (const float*)d_in[4];
    const float* Ui = (const float*)d_in[5];
    const float* bi = (const float*)d_in[6];
    const float* Wo = (const float*)d_in[7];
    const float* Uo = (const float*)d_in[8];
    const float* bo = (const float*)d_in[9];
    const float* Wc = (const float*)d_in[10];
    const float* Uc = (const float*)d_in[11];
    const float* bc = (const float*)d_in[12];

    pack_kernel<<<1024, 256>>>(Wf, Wi, Wc, Wo, Uf, Ui, Uc, Uo, bf, bi, bc, bo);
    gemm_xg_kernel<<<dim3(G4 / BN, (S * B) / BM), 256>>>(x);
    lstm_kernel<<<NCTA, NTHR2>>>((float*)d_out, out_size);
}